// round 2
// baseline (speedup 1.0000x reference)
#include <cuda_runtime.h>
#include <cstdint>

// ---- static problem config ----
#define B_   2
#define N_   6
#define D_   48
#define FH_  16
#define FW_  44
#define C_   80
#define NX_  256
#define NY_  256
#define NPRIME (B_*N_*D_*FH_*FW_)       // 405504 points
#define NVOX   (B_*NY_*NX_)             // 131072 voxels (NZ=1)
#define CVEC   (C_/4)                   // 20 float4 per point row

// ---- device scratch ----
__device__ int   g_flat[NPRIME];        // voxel id or -1
__device__ int   g_cnt[NVOX];           // per-voxel count
__device__ int   g_off[NVOX];           // exclusive prefix
__device__ int   g_cur[NVOX];           // fill cursor (copy of g_off)
__device__ int   g_idx[NPRIME];         // point ids grouped by voxel
__device__ int   g_bsum[256];           // scan block sums
__device__ float g_xf[B_*N_*24];        // invPost[9], comb[9], trans[3], post_trans[3]

// ---------------------------------------------------------------------------
__device__ __forceinline__ void inv3(const float* m, float* o) {
    float a=m[0], b=m[1], c=m[2];
    float d=m[3], e=m[4], f=m[5];
    float g=m[6], h=m[7], i=m[8];
    float A  =  (e*i - f*h);
    float Bc = -(d*i - f*g);
    float Cc =  (d*h - e*g);
    float det = a*A + b*Bc + c*Cc;
    float r = 1.0f / det;
    o[0] = A*r;            o[1] = (c*h - b*i)*r;  o[2] = (b*f - c*e)*r;
    o[3] = Bc*r;           o[4] = (a*i - c*g)*r;  o[5] = (c*d - a*f)*r;
    o[6] = Cc*r;           o[7] = (b*g - a*h)*r;  o[8] = (a*e - b*d)*r;
}

// Zero per-voxel counters; block 0 additionally computes per-camera transforms.
__global__ void zero_setup_kernel(const float* __restrict__ rots,
                                  const float* __restrict__ trans,
                                  const float* __restrict__ intrins,
                                  const float* __restrict__ post_rots,
                                  const float* __restrict__ post_trans) {
    int i = blockIdx.x * blockDim.x + threadIdx.x;
    if (i < NVOX) g_cnt[i] = 0;
    if (blockIdx.x == 0 && threadIdx.x < B_*N_) {
        int t = threadIdx.x;
        float invP[9], invK[9], comb[9];
        inv3(post_rots + t*9, invP);
        inv3(intrins  + t*9, invK);
        const float* R = rots + t*9;
        #pragma unroll
        for (int r_ = 0; r_ < 3; r_++)
            #pragma unroll
            for (int j = 0; j < 3; j++) {
                float s = 0.0f;
                #pragma unroll
                for (int k = 0; k < 3; k++) s += R[r_*3+k] * invK[k*3+j];
                comb[r_*3+j] = s;
            }
        float* o = g_xf + t*24;
        #pragma unroll
        for (int k = 0; k < 9; k++) { o[k] = invP[k]; o[9+k] = comb[k]; }
        #pragma unroll
        for (int k = 0; k < 3; k++) { o[18+k] = trans[t*3+k]; o[21+k] = post_trans[t*3+k]; }
    }
}

// ---------------------------------------------------------------------------
// Geometry + histogram: per point compute voxel id, count it.
__global__ void geom_hist_kernel() {
    int p = blockIdx.x * blockDim.x + threadIdx.x;
    if (p >= NPRIME) return;

    int w  = p % FW_;
    int h  = (p / FW_) % FH_;
    int d  = (p / (FW_*FH_)) % D_;
    int bn = p / (FW_*FH_*D_);
    int b  = bn / N_;

    const float* xf = g_xf + bn*24;

    float xs = (float)w * (float)(703.0 / 43.0);
    float ys = (float)h * 17.0f;
    float ds = 2.0f + (float)(56.0 / 48.0) * (float)d;

    float px = xs - xf[21];
    float py = ys - xf[22];
    float pz = ds - xf[23];
    float qx = xf[0]*px + xf[1]*py + xf[2]*pz;
    float qy = xf[3]*px + xf[4]*py + xf[5]*pz;
    float qz = xf[6]*px + xf[7]*py + xf[8]*pz;
    qx *= qz; qy *= qz;
    float rx = xf[9 ]*qx + xf[10]*qy + xf[11]*qz + xf[18];
    float ry = xf[12]*qx + xf[13]*qy + xf[14]*qz + xf[19];
    float rz = xf[15]*qx + xf[16]*qy + xf[17]*qz + xf[20];

    int gx = (int)((rx - (-51.2f)) / 0.4f);
    int gy = (int)((ry - (-51.2f)) / 0.4f);
    int gz = (int)((rz - (-10.0f)) / 20.0f);

    bool kept = (gx >= 0) & (gx < NX_) & (gy >= 0) & (gy < NY_) & (gz >= 0) & (gz < 1);
    int flat = kept ? ((b * NY_ + gy) * NX_ + gx) : -1;
    g_flat[p] = flat;
    if (flat >= 0) atomicAdd(&g_cnt[flat], 1);
}

// ---------------------------------------------------------------------------
// Prefix sum over g_cnt[NVOX]: 256 chunks of 512.
__global__ void scan1_kernel() {               // 256 blocks x 512 thr: chunk sums
    __shared__ int s[512];
    int t = threadIdx.x;
    s[t] = g_cnt[blockIdx.x * 512 + t];
    __syncthreads();
    for (int st = 256; st > 0; st >>= 1) {
        if (t < st) s[t] += s[t + st];
        __syncthreads();
    }
    if (t == 0) g_bsum[blockIdx.x] = s[0];
}

__global__ void scan2_kernel() {               // 1 block x 256 thr: exclusive scan of sums
    __shared__ int s[256];
    int t = threadIdx.x;
    int orig = g_bsum[t];
    s[t] = orig;
    __syncthreads();
    for (int st = 1; st < 256; st <<= 1) {
        int v = (t >= st) ? s[t - st] : 0;
        __syncthreads();
        s[t] += v;
        __syncthreads();
    }
    g_bsum[t] = s[t] - orig;                   // exclusive
}

__global__ void scan3_kernel() {               // 256 blocks x 512 thr: final offsets
    __shared__ int s[512];
    int t = threadIdx.x;
    int i = blockIdx.x * 512 + t;
    int orig = g_cnt[i];
    s[t] = orig;
    __syncthreads();
    for (int st = 1; st < 512; st <<= 1) {
        int v = (t >= st) ? s[t - st] : 0;
        __syncthreads();
        s[t] += v;
        __syncthreads();
    }
    int off = s[t] - orig + g_bsum[blockIdx.x];
    g_off[i] = off;
    g_cur[i] = off;
}

// ---------------------------------------------------------------------------
__global__ void fill_kernel() {
    int p = blockIdx.x * blockDim.x + threadIdx.x;
    if (p >= NPRIME) return;
    int f = g_flat[p];
    if (f >= 0) {
        int pos = atomicAdd(&g_cur[f], 1);
        g_idx[pos] = p;
    }
}

// ---------------------------------------------------------------------------
// Gather + fused transpose. One block per (b, y, 32-wide x strip).
// Warp handles voxels xl = warp + 8*i. Lanes 0..19 each own a float4 channel
// chunk; per point one coalesced 320B row read. Output written coalesced in
// [B, C, NY, NX] via an SMEM tile.
__global__ void gather_kernel(const float4* __restrict__ x4, float* __restrict__ out) {
    __shared__ float tile[C_][33];
    int blk = blockIdx.x;
    int xb = blk & 7;
    int y  = (blk >> 3) & (NY_ - 1);
    int b  = blk >> 11;
    int x0 = xb * 32;
    int warp = threadIdx.x >> 5;
    int lane = threadIdx.x & 31;

    #pragma unroll
    for (int i = 0; i < 4; i++) {
        int xl = warp + i * 8;
        int v  = (b * NY_ + y) * NX_ + x0 + xl;
        int start = g_off[v];
        int cnt   = g_cnt[v];
        float4 acc = make_float4(0.f, 0.f, 0.f, 0.f);
        if (lane < 20) {
            const int* ip = g_idx + start;
            int j = 0;
            for (; j + 4 <= cnt; j += 4) {
                int p0 = ip[j+0], p1 = ip[j+1], p2 = ip[j+2], p3 = ip[j+3];
                float4 a0 = x4[(size_t)p0 * CVEC + lane];
                float4 a1 = x4[(size_t)p1 * CVEC + lane];
                float4 a2 = x4[(size_t)p2 * CVEC + lane];
                float4 a3 = x4[(size_t)p3 * CVEC + lane];
                acc.x += a0.x + a1.x + a2.x + a3.x;
                acc.y += a0.y + a1.y + a2.y + a3.y;
                acc.z += a0.z + a1.z + a2.z + a3.z;
                acc.w += a0.w + a1.w + a2.w + a3.w;
            }
            for (; j < cnt; j++) {
                int pid = ip[j];
                float4 a = x4[(size_t)pid * CVEC + lane];
                acc.x += a.x; acc.y += a.y; acc.z += a.z; acc.w += a.w;
            }
            tile[4*lane+0][xl] = acc.x;
            tile[4*lane+1][xl] = acc.y;
            tile[4*lane+2][xl] = acc.z;
            tile[4*lane+3][xl] = acc.w;
        }
    }
    __syncthreads();

    float* ob = out + (size_t)b * C_ * NY_ * NX_ + (size_t)y * NX_ + x0;
    for (int e = threadIdx.x; e < C_ * 32; e += 256) {
        int c  = e >> 5;
        int xl = e & 31;
        ob[(size_t)c * (NY_ * NX_) + xl] = tile[c][xl];
    }
}

// ---------------------------------------------------------------------------
extern "C" void kernel_launch(void* const* d_in, const int* in_sizes, int n_in,
                              void* d_out, int out_size) {
    const float* x          = (const float*)d_in[0];
    const float* rots       = (const float*)d_in[1];
    const float* trans      = (const float*)d_in[2];
    const float* intrins    = (const float*)d_in[3];
    const float* post_rots  = (const float*)d_in[4];
    const float* post_trans = (const float*)d_in[5];
    float* out = (float*)d_out;

    zero_setup_kernel<<<NVOX/256, 256>>>(rots, trans, intrins, post_rots, post_trans);
    geom_hist_kernel<<<(NPRIME + 255) / 256, 256>>>();
    scan1_kernel<<<256, 512>>>();
    scan2_kernel<<<1, 256>>>();
    scan3_kernel<<<256, 512>>>();
    fill_kernel<<<(NPRIME + 255) / 256, 256>>>();
    gather_kernel<<<B_ * NY_ * (NX_ / 32), 256>>>((const float4*)x, out);
}

// round 3
// speedup vs baseline: 2.9432x; 2.9432x over previous
#include <cuda_runtime.h>
#include <cstdint>

// ---- static problem config ----
#define B_   2
#define N_   6
#define D_   48
#define FH_  16
#define FW_  44
#define C_   80
#define NX_  256
#define NY_  256
#define NPRIME (B_*N_*D_*FH_*FW_)       // 405504 points
#define NGROUP (B_*N_*D_*FW_)           // 25344 (b,n,d,w) groups of 16 h-points
#define CVEC   (C_/4)                   // 20 float4 per point row
#define PLANE  (NY_*NX_)                // 65536

// ---- device scratch ----
__device__ int   g_flat[NPRIME];        // per-point voxel id (b*NY+gy)*NX+gx or -1
__device__ float g_xf[B_*N_*24];        // invPost[9], comb[9], trans[3], post_trans[3]

// ---------------------------------------------------------------------------
__device__ __forceinline__ void inv3(const float* m, float* o) {
    float a=m[0], b=m[1], c=m[2];
    float d=m[3], e=m[4], f=m[5];
    float g=m[6], h=m[7], i=m[8];
    float A  =  (e*i - f*h);
    float Bc = -(d*i - f*g);
    float Cc =  (d*h - e*g);
    float det = a*A + b*Bc + c*Cc;
    float r = 1.0f / det;
    o[0] = A*r;            o[1] = (c*h - b*i)*r;  o[2] = (b*f - c*e)*r;
    o[3] = Bc*r;           o[4] = (a*i - c*g)*r;  o[5] = (c*d - a*f)*r;
    o[6] = Cc*r;           o[7] = (b*g - a*h)*r;  o[8] = (a*e - b*d)*r;
}

// Zero the output; block 0 also computes per-camera transforms.
__global__ void zero_setup_kernel(float4* __restrict__ out4,
                                  const float* __restrict__ rots,
                                  const float* __restrict__ trans,
                                  const float* __restrict__ intrins,
                                  const float* __restrict__ post_rots,
                                  const float* __restrict__ post_trans) {
    int i = blockIdx.x * blockDim.x + threadIdx.x;
    if (i < (B_ * C_ * PLANE) / 4) out4[i] = make_float4(0.f, 0.f, 0.f, 0.f);
    if (blockIdx.x == 0 && threadIdx.x < B_*N_) {
        int t = threadIdx.x;
        float invP[9], invK[9], comb[9];
        inv3(post_rots + t*9, invP);
        inv3(intrins  + t*9, invK);
        const float* R = rots + t*9;
        #pragma unroll
        for (int r_ = 0; r_ < 3; r_++)
            #pragma unroll
            for (int j = 0; j < 3; j++) {
                float s = 0.0f;
                #pragma unroll
                for (int k = 0; k < 3; k++) s += R[r_*3+k] * invK[k*3+j];
                comb[r_*3+j] = s;
            }
        float* o = g_xf + t*24;
        #pragma unroll
        for (int k = 0; k < 9; k++) { o[k] = invP[k]; o[9+k] = comb[k]; }
        #pragma unroll
        for (int k = 0; k < 3; k++) { o[18+k] = trans[t*3+k]; o[21+k] = post_trans[t*3+k]; }
    }
}

// ---------------------------------------------------------------------------
// Per-point geometry -> voxel flat index (or -1).
__global__ void geom_kernel() {
    int p = blockIdx.x * blockDim.x + threadIdx.x;
    if (p >= NPRIME) return;

    int w  = p % FW_;
    int h  = (p / FW_) % FH_;
    int d  = (p / (FW_*FH_)) % D_;
    int bn = p / (FW_*FH_*D_);
    int b  = bn / N_;

    const float* xf = g_xf + bn*24;

    float xs = (float)w * (float)(703.0 / 43.0);
    float ys = (float)h * 17.0f;
    float ds = 2.0f + (float)(56.0 / 48.0) * (float)d;

    float px = xs - xf[21];
    float py = ys - xf[22];
    float pz = ds - xf[23];
    float qx = xf[0]*px + xf[1]*py + xf[2]*pz;
    float qy = xf[3]*px + xf[4]*py + xf[5]*pz;
    float qz = xf[6]*px + xf[7]*py + xf[8]*pz;
    qx *= qz; qy *= qz;
    float rx = xf[9 ]*qx + xf[10]*qy + xf[11]*qz + xf[18];
    float ry = xf[12]*qx + xf[13]*qy + xf[14]*qz + xf[19];
    float rz = xf[15]*qx + xf[16]*qy + xf[17]*qz + xf[20];

    int gx = (int)((rx - (-51.2f)) / 0.4f);
    int gy = (int)((ry - (-51.2f)) / 0.4f);
    int gz = (int)((rz - (-10.0f)) / 20.0f);

    bool kept = (gx >= 0) & (gx < NX_) & (gy >= 0) & (gy < NY_) & (gz >= 0) & (gz < 1);
    g_flat[p] = kept ? ((b * NY_ + gy) * NX_ + gx) : -1;
}

// ---------------------------------------------------------------------------
// Emit acc (channels 4k..4k+3) for voxel 'flat' directly into [B,C,NY,NX].
__device__ __forceinline__ void flush_acc(float* __restrict__ out, int flat, int k,
                                          const float4& acc) {
    int b   = flat / PLANE;           // batch encoded in flat id
    int vox = flat - b * PLANE;       // gy*NX + gx
    float* dst = out + ((size_t)(b * C_ + 4*k)) * PLANE + vox;
    asm volatile("red.global.add.f32 [%0], %1;" :: "l"(dst),           "f"(acc.x) : "memory");
    asm volatile("red.global.add.f32 [%0], %1;" :: "l"(dst + PLANE),   "f"(acc.y) : "memory");
    asm volatile("red.global.add.f32 [%0], %1;" :: "l"(dst + 2*PLANE), "f"(acc.z) : "memory");
    asm volatile("red.global.add.f32 [%0], %1;" :: "l"(dst + 3*PLANE), "f"(acc.w) : "memory");
}

// One thread per (group=(b,n,d,w), float4-chunk). Sums the 16 h-points of the
// group that share a voxel id in registers, then one reduction per run.
__global__ void hsum_scatter_kernel(const float4* __restrict__ x4,
                                    float* __restrict__ out) {
    int t = blockIdx.x * blockDim.x + threadIdx.x;   // < NGROUP*CVEC (exact grid)
    int g = t / CVEC;
    int k = t - g * CVEC;

    int w   = g % FW_;
    int dnb = g / FW_;                 // bn*D + d
    int base_p = dnb * (FH_*FW_) + w;  // point index at h=0

    // load all 16 voxel ids
    int fl[FH_];
    #pragma unroll
    for (int h = 0; h < FH_; h++) fl[h] = g_flat[base_p + h*FW_];

    bool uniform = true;
    #pragma unroll
    for (int h = 1; h < FH_; h++) uniform &= (fl[h] == fl[0]);

    const float4* xp = x4 + (size_t)base_p * CVEC + k;
    const size_t hstride = (size_t)FW_ * CVEC;

    if (uniform) {
        if (fl[0] < 0) return;
        // fast path: 16 independent loads -> high MLP, single flush
        float4 acc = make_float4(0.f, 0.f, 0.f, 0.f);
        #pragma unroll
        for (int h = 0; h < FH_; h++) {
            float4 a = xp[h * hstride];
            acc.x += a.x; acc.y += a.y; acc.z += a.z; acc.w += a.w;
        }
        flush_acc(out, fl[0], k, acc);
    } else {
        // general path: run-length flush over h
        float4 acc = make_float4(0.f, 0.f, 0.f, 0.f);
        int cur = -1;
        #pragma unroll
        for (int h = 0; h < FH_; h++) {
            int f = fl[h];
            if (f < 0) continue;
            if (f != cur) {
                if (cur >= 0) flush_acc(out, cur, k, acc);
                acc = make_float4(0.f, 0.f, 0.f, 0.f);
                cur = f;
            }
            float4 a = xp[h * hstride];
            acc.x += a.x; acc.y += a.y; acc.z += a.z; acc.w += a.w;
        }
        if (cur >= 0) flush_acc(out, cur, k, acc);
    }
}

// ---------------------------------------------------------------------------
extern "C" void kernel_launch(void* const* d_in, const int* in_sizes, int n_in,
                              void* d_out, int out_size) {
    const float* x          = (const float*)d_in[0];
    const float* rots       = (const float*)d_in[1];
    const float* trans      = (const float*)d_in[2];
    const float* intrins    = (const float*)d_in[3];
    const float* post_rots  = (const float*)d_in[4];
    const float* post_trans = (const float*)d_in[5];
    float* out = (float*)d_out;

    zero_setup_kernel<<<(B_*C_*PLANE/4 + 255) / 256, 256>>>(
        (float4*)out, rots, trans, intrins, post_rots, post_trans);
    geom_kernel<<<(NPRIME + 255) / 256, 256>>>();
    hsum_scatter_kernel<<<(NGROUP * CVEC) / 256, 256>>>((const float4*)x, out);
}